// round 6
// baseline (speedup 1.0000x reference)
#include <cuda_runtime.h>
#include <cuda_bf16.h>
#include <math.h>

// Fixed shape (setup_inputs): B=8, H=W=96, D=768, 25 shifts, temp 0.07
#define BB 8
#define HH 96
#define WW 96
#define DD 768
#define NN (HH*WW)
#define TH 16              // tile rows
#define TW 32              // tile cols
#define HR (TH+4)          // halo rows = 20
#define HC (TW+4)          // halo cols = 36
#define RS 38              // padded smem row stride
#define PS (HR*RS)         // plane stride = 760
#define HGAP 16            // bank decorrelation for planes 4..7
#define BUFSZ (8*PS+HGAP)  // 6096 floats
#define NSTG 6             // staging float4 slots per thread (per group)
#define NITER 48           // chunks per D-half (8 floats each)
#define NBLK (3*6*BB)      // 144 blocks
// scratch layout inside the 4-buffer smem region (reused post-loop)
#define SCR_MERGE 0            // 256*53 = 13568 floats
#define SCR_SA    13568        // 2*1440 = 2880 floats
#define SCR_SINV  16448        // 720 floats
#define SCR_RED   17200        // 5*16 floats
#define SMEM_FLT  (4*BUFSZ)    // 24384 floats = 97536 B

__device__ float g_part[5][NBLK];   // a1, a2, p, s1, s2 per block

__device__ __forceinline__ float f4c(const float4 v, int i) {
    return i == 0 ? v.x : i == 1 ? v.y : i == 2 ? v.z : v.w;
}

extern __shared__ float smem[];

__global__ void __launch_bounds__(512, 1)
align_kernel(const float* __restrict__ z1, const float* __restrict__ z2,
             const float* __restrict__ w1, const float* __restrict__ w2) {
    const int tid = threadIdx.x;
    const int g   = tid >> 8;        // D-split group: 0 -> d[0,384), 1 -> d[384,768)
    const int gt  = tid & 255;
    const int b   = blockIdx.z;
    const int th0 = blockIdx.y * TH, tw0 = blockIdx.x * TW;
    const int tr  = gt >> 4;         // 0..15 tile row
    const int tc  = gt & 15;
    const int wl  = tc * 2;          // first of 2 tokens

    float* bufA = smem + (g * 2    ) * BUFSZ;
    float* bufB = smem + (g * 2 + 1) * BUFSZ;

    // staging map: float4 slot q = gt + 256k  ->  halo token t = q>>1, half = q&1
    int goff[NSTG], soff[NSTG];
#pragma unroll
    for (int k = 0; k < NSTG; k++) {
        int q = gt + (k << 8);
        if (q < 2 * HR * HC) {
            int t = q >> 1, half = q & 1;
            int r = t / HC, cl = t - r * HC;
            int gh = th0 + r - 2, gw = tw0 + cl - 2;
            bool inb = ((unsigned)gh < HH) && ((unsigned)gw < WW);
            goff[k] = inb ? ((b * NN + gh * WW + gw) * DD + g * 384 + half * 4) : -1;
            soff[k] = half * (4 * PS + HGAP) + r * RS + cl;
        } else { goff[k] = -1; soff[k] = -1; }
    }

    const float* z1p =
        z1 + (size_t)(b * NN + (th0 + tr) * WW + (tw0 + wl)) * DD + g * 384;

    float sims[50];
#pragma unroll
    for (int s = 0; s < 50; s++) sims[s] = 0.f;
    float ss1_0 = 0.f, ss1_1 = 0.f;
    float ss2h[NSTG];
#pragma unroll
    for (int k = 0; k < NSTG; k++) ss2h[k] = 0.f;

    // prologue: stage chunk 0 into bufA (immediate LDG->STS) + z1 chunk 0
#pragma unroll
    for (int k = 0; k < NSTG; k++)
        if (soff[k] >= 0) {
            float4 v = (goff[k] >= 0) ? *(const float4*)(z2 + goff[k])
                                      : make_float4(0.f, 0.f, 0.f, 0.f);
            float* d0 = bufA + soff[k];
            d0[0] = v.x; d0[PS] = v.y; d0[2 * PS] = v.z; d0[3 * PS] = v.w;
            ss2h[k] += v.x * v.x + v.y * v.y + v.z * v.z + v.w * v.w;
        }
    float4 z1c[4];
    z1c[0] = *(const float4*)(z1p);
    z1c[1] = *(const float4*)(z1p + 4);
    z1c[2] = *(const float4*)(z1p + DD);
    z1c[3] = *(const float4*)(z1p + DD + 4);
    __syncthreads();

#pragma unroll 1
    for (int c = 0; c < NITER; c++) {
        const float* base = ((c & 1) ? bufB : bufA) + tr * RS + wl;
        float* nxt = (c & 1) ? bufA : bufB;
        const bool more = (c + 1 < NITER);

        // stage chunk c+1 into the other buffer (immediate, latency hidden)
        if (more) {
#pragma unroll
            for (int k = 0; k < NSTG; k++)
                if (soff[k] >= 0) {
                    float4 v = (goff[k] >= 0)
                        ? *(const float4*)(z2 + goff[k] + (size_t)(c + 1) * 8)
                        : make_float4(0.f, 0.f, 0.f, 0.f);
                    float* d0 = nxt + soff[k];
                    d0[0] = v.x; d0[PS] = v.y; d0[2 * PS] = v.z; d0[3 * PS] = v.w;
                    ss2h[k] += v.x * v.x + v.y * v.y + v.z * v.z + v.w * v.w;
                }
        }

        // d = 0..3 (z1c[0], z1c[2]), planes 0..3
#pragma unroll
        for (int d = 0; d < 4; d++) {
            float a0 = f4c(z1c[0], d), a1 = f4c(z1c[2], d);
            ss1_0 += a0 * a0; ss1_1 += a1 * a1;
            const float* pd = base + d * PS;
#pragma unroll
            for (int dy = 0; dy < 5; dy++) {
                const float* row = pd + dy * RS;
                float2 q0 = *(const float2*)(row);
                float2 q1 = *(const float2*)(row + 2);
                float2 q2 = *(const float2*)(row + 4);
                int s = dy * 5;
                sims[s    ] += a0 * q0.x; sims[s + 1] += a0 * q0.y;
                sims[s + 2] += a0 * q1.x; sims[s + 3] += a0 * q1.y;
                sims[s + 4] += a0 * q2.x;
                sims[25 + s] += a1 * q0.y; sims[26 + s] += a1 * q1.x;
                sims[27 + s] += a1 * q1.y; sims[28 + s] += a1 * q2.x;
                sims[29 + s] += a1 * q2.y;
            }
        }
        if (more) {
            z1c[0] = *(const float4*)(z1p + (size_t)(c + 1) * 8);
            z1c[2] = *(const float4*)(z1p + DD + (size_t)(c + 1) * 8);
        }
        // d = 4..7 (z1c[1], z1c[3]), planes 4..7 (+HGAP)
#pragma unroll
        for (int d = 0; d < 4; d++) {
            float a0 = f4c(z1c[1], d), a1 = f4c(z1c[3], d);
            ss1_0 += a0 * a0; ss1_1 += a1 * a1;
            const float* pd = base + HGAP + (d + 4) * PS;
#pragma unroll
            for (int dy = 0; dy < 5; dy++) {
                const float* row = pd + dy * RS;
                float2 q0 = *(const float2*)(row);
                float2 q1 = *(const float2*)(row + 2);
                float2 q2 = *(const float2*)(row + 4);
                int s = dy * 5;
                sims[s    ] += a0 * q0.x; sims[s + 1] += a0 * q0.y;
                sims[s + 2] += a0 * q1.x; sims[s + 3] += a0 * q1.y;
                sims[s + 4] += a0 * q2.x;
                sims[25 + s] += a1 * q0.y; sims[26 + s] += a1 * q1.x;
                sims[27 + s] += a1 * q1.y; sims[28 + s] += a1 * q2.x;
                sims[29 + s] += a1 * q2.y;
            }
        }
        if (more) {
            z1c[1] = *(const float4*)(z1p + (size_t)(c + 1) * 8 + 4);
            z1c[3] = *(const float4*)(z1p + DD + (size_t)(c + 1) * 8 + 4);
        }
        __syncthreads();
    }

    // ---- exchange: z2 norm partials + group-1 sims -> scratch -------------
#pragma unroll
    for (int k = 0; k < NSTG; k++) {
        int q = gt + (k << 8);
        if (q < 2 * HR * HC) smem[SCR_SA + g * 1440 + q] = ss2h[k];
    }
    if (g == 1) {
        float* s = smem + SCR_MERGE + gt * 53;
#pragma unroll
        for (int i = 0; i < 50; i++) s[i] = sims[i];
        s[50] = ss1_0; s[51] = ss1_1;
    }
    __syncthreads();

    // z2 halo inverse norms (combine 2 halves x 2 groups)
    for (int t = tid; t < HR * HC; t += 512) {
        float n2 = smem[SCR_SA + 2 * t] + smem[SCR_SA + 2 * t + 1]
                 + smem[SCR_SA + 1440 + 2 * t] + smem[SCR_SA + 1440 + 2 * t + 1];
        smem[SCR_SINV + t] = 1.f / fmaxf(sqrtf(n2), 1e-12f);
    }
    // group 0 merges group 1's sims/ss1
    if (g == 0) {
        const float* s = smem + SCR_MERGE + gt * 53;
#pragma unroll
        for (int i = 0; i < 50; i++) sims[i] += s[i];
        ss1_0 += s[50]; ss1_1 += s[51];
    }
    __syncthreads();

    // ---- epilogue: softmax + weighted partials (group 0 only) -------------
    float pA1 = 0.f, pA2 = 0.f, pP = 0.f, pS1 = 0.f, pS2 = 0.f;
    if (g == 0) {
        const float inv1_0 = 1.f / fmaxf(sqrtf(ss1_0), 1e-12f);
        const float inv1_1 = 1.f / fmaxf(sqrtf(ss1_1), 1e-12f);
        const float invT   = 1.f / 0.07f;  // SHIFT_TEMP + 1e-10 == 0.07f in fp32
#pragma unroll
        for (int j = 0; j < 2; j++) {
            float inv1 = j ? inv1_1 : inv1_0;
            float sn[25];
            float m = -1e30f;
#pragma unroll
            for (int dy = 0; dy < 5; dy++)
#pragma unroll
                for (int dx = 0; dx < 5; dx++) {
                    int t = (tr + dy) * HC + (wl + j + dx);
                    float v = sims[j * 25 + dy * 5 + dx] * inv1 * smem[SCR_SINV + t];
                    sn[dy * 5 + dx] = v;
                    m = fmaxf(m, v);
                }
            float se = 0.f, sv = 0.f;
#pragma unroll
            for (int s = 0; s < 25; s++) {
                float e = __expf((sn[s] - m) * invT);
                se += e; sv += e * sn[s];
            }
            float sb = sv / se;
            int tok = (th0 + tr) * WW + tw0 + wl + j;
            float wv1 = w1[b * NN + tok], wv2 = w2[b * NN + tok];
            pA1 += (1.f - sb) * wv1;
            pA2 += (1.f - sb) * wv2;
            pP  += sb;
            pS1 += wv1;
            pS2 += wv2;
        }
    }

    // ---- deterministic block reduction (5 values, 16 warps, no atomics) ---
#pragma unroll
    for (int o = 16; o > 0; o >>= 1) {
        pA1 += __shfl_down_sync(0xffffffffu, pA1, o);
        pA2 += __shfl_down_sync(0xffffffffu, pA2, o);
        pP  += __shfl_down_sync(0xffffffffu, pP,  o);
        pS1 += __shfl_down_sync(0xffffffffu, pS1, o);
        pS2 += __shfl_down_sync(0xffffffffu, pS2, o);
    }
    float* red = smem + SCR_RED;
    int wid = tid >> 5;
    if ((tid & 31) == 0) {
        red[wid] = pA1; red[16 + wid] = pA2; red[32 + wid] = pP;
        red[48 + wid] = pS1; red[64 + wid] = pS2;
    }
    __syncthreads();
    if (tid == 0) {
        float a1 = 0.f, a2 = 0.f, p = 0.f, s1 = 0.f, s2 = 0.f;
#pragma unroll
        for (int i = 0; i < 16; i++) {
            a1 += red[i]; a2 += red[16 + i]; p += red[32 + i];
            s1 += red[48 + i]; s2 += red[64 + i];
        }
        int bid = blockIdx.x + 3 * blockIdx.y + 18 * blockIdx.z;
        g_part[0][bid] = a1; g_part[1][bid] = a2; g_part[2][bid] = p;
        g_part[3][bid] = s1; g_part[4][bid] = s2;
    }
}

// ---------------------------------------------------------------------------
// Finalize: per-batch combine with deferred weight-normalization division
// ---------------------------------------------------------------------------
__global__ void finalize_kernel(float* __restrict__ out) {
    int tid = threadIdx.x;
    int w = tid >> 5, lane = tid & 31;     // warp w = batch w (w < 8)
    __shared__ float sh[16];
    float a1 = 0.f, a2 = 0.f, p = 0.f, s1 = 0.f, s2 = 0.f;
    if (w < BB && lane < 18) {             // 18 blocks per batch
        int bid = w * 18 + lane;
        a1 = g_part[0][bid]; a2 = g_part[1][bid]; p = g_part[2][bid];
        s1 = g_part[3][bid]; s2 = g_part[4][bid];
    }
#pragma unroll
    for (int o = 16; o > 0; o >>= 1) {
        a1 += __shfl_down_sync(0xffffffffu, a1, o);
        a2 += __shfl_down_sync(0xffffffffu, a2, o);
        p  += __shfl_down_sync(0xffffffffu, p,  o);
        s1 += __shfl_down_sync(0xffffffffu, s1, o);
        s2 += __shfl_down_sync(0xffffffffu, s2, o);
    }
    if (lane == 0 && w < BB) {
        sh[w]     = 0.5f * (a1 / (s1 + 1e-10f) + a2 / (s2 + 1e-10f)); // align_b
        sh[8 + w] = p;                                                 // pos sum
    }
    __syncthreads();
    if (tid == 0) {
        float ta = 0.f, tp = 0.f;
#pragma unroll
        for (int i = 0; i < BB; i++) { ta += sh[i]; tp += sh[8 + i]; }
        out[0] = ta / (float)BB;
        out[1] = tp / (float)(BB * NN);
    }
}

// ---------------------------------------------------------------------------
extern "C" void kernel_launch(void* const* d_in, const int* in_sizes, int n_in,
                              void* d_out, int out_size) {
    const float* z1 = (const float*)d_in[0];
    const float* z2 = (const float*)d_in[1];
    const float* w1 = (const float*)d_in[2];
    const float* w2 = (const float*)d_in[3];
    float* out = (float*)d_out;

    static int smem_set = 0;
    if (!smem_set) {
        cudaFuncSetAttribute(align_kernel,
                             cudaFuncAttributeMaxDynamicSharedMemorySize,
                             SMEM_FLT * sizeof(float));
        smem_set = 1;
    }
    dim3 grid(WW / TW, HH / TH, BB);       // (3, 6, 8) = 144 blocks
    align_kernel<<<grid, 512, SMEM_FLT * sizeof(float)>>>(z1, z2, w1, w2);
    finalize_kernel<<<1, 256>>>(out);
}

// round 9
// speedup vs baseline: 1.4047x; 1.4047x over previous
#include <cuda_runtime.h>
#include <cstdint>
#include <math.h>

#define BB 8
#define HH 96
#define WW 96
#define DD 768
#define NN (HH*WW)
#define STR 36             // smem row stride (floats), ==4 mod 32 -> conflict-free frags
#define AROWS 128
#define BROWS 240          // 20x12 halo
#define ROWS 368
#define BUFF (ROWS*STR)    // 13248 floats per buffer
#define NCHK 24            // K chunks of 32 floats
#define S_NRM (2*BUFF)     // norms: 368 floats
#define S_RED (S_NRM+ROWS)
#define SMEMF (S_RED+48)   // 26912 floats = 107648 B
#define SIMSTR 76          // sims scratch stride (reuses buf0 region)
#define NBLK 576
#define TFM(x) __uint_as_float(__float_as_uint(x) & 0xFFFFE000u)

__device__ float g_part[5][NBLK];
extern __shared__ float smem[];

__device__ __forceinline__ void mma8(float* d, uint32_t a0, uint32_t a1,
                                     uint32_t a2, uint32_t a3,
                                     uint32_t b0, uint32_t b1) {
  asm volatile(
    "mma.sync.aligned.m16n8k8.row.col.f32.tf32.tf32.f32 "
    "{%0,%1,%2,%3}, {%4,%5,%6,%7}, {%8,%9}, {%0,%1,%2,%3};"
    : "+f"(d[0]), "+f"(d[1]), "+f"(d[2]), "+f"(d[3])
    : "r"(a0), "r"(a1), "r"(a2), "r"(a3), "r"(b0), "r"(b1));
}

__global__ void __launch_bounds__(256, 2)
align_kernel(const float* __restrict__ z1, const float* __restrict__ z2,
             const float* __restrict__ w1, const float* __restrict__ w2)
{
  const int tid = threadIdx.x, w = tid >> 5, lane = tid & 31, lane8 = tid & 7;
  const int b = blockIdx.z, th0 = blockIdx.y * 16, tw0 = blockIdx.x * 8;

  // ---- staging tables: slot k -> row = (tid>>3) + 32k ----------------------
  // k 0..3: A rows (z1, always valid); k 4..11: B rows (z2 halo, zero-fill OOB)
  int goff[12], sof[12];
#pragma unroll
  for (int k = 0; k < 4; k++) {
    int row = (tid >> 3) + 32 * k;
    int ty = row >> 3, tx = row & 7;
    goff[k] = (b*NN + (th0+ty)*WW + tw0+tx)*DD + lane8*4;
    sof[k]  = row*STR + lane8*4;
  }
#pragma unroll
  for (int k = 4; k < 12; k++) {
    int row = (tid >> 3) + 32 * k;
    if (row < ROWS) {
      int n = row - AROWS, r = n / 12, cl = n - 12*r;
      int gh = th0 + r - 2, gw = tw0 + cl - 2;
      bool inb = ((unsigned)gh < HH) && ((unsigned)gw < WW);
      goff[k] = inb ? (b*NN + gh*WW + gw)*DD + lane8*4 : -1;
      sof[k]  = row*STR + lane8*4;
    } else { goff[k] = -1; sof[k] = -1; }
  }
  float nrm[12];
#pragma unroll
  for (int k = 0; k < 12; k++) nrm[k] = 0.f;

  float acc[9][4];
#pragma unroll
  for (int j = 0; j < 9; j++)
#pragma unroll
    for (int i = 0; i < 4; i++) acc[j][i] = 0.f;

  // per-lane fragment base offsets (float index), conflict-free with STR=36
  const int aOff = (16*w + (lane >> 2))*STR + (lane & 3);
  const int bOff = (AROWS + 24*w + (lane >> 2))*STR + (lane & 3);

  // ---- prologue: stage chunk 0 into buf0 -----------------------------------
  {
    float* bp = smem;
#pragma unroll
    for (int k = 0; k < 12; k++) {
      if (k >= 4 && sof[k] < 0) continue;
      float4 v = (k < 4 || goff[k] >= 0)
        ? *(const float4*)(((k < 4) ? z1 : z2) + goff[k])
        : make_float4(0.f, 0.f, 0.f, 0.f);
      v.x = TFM(v.x); v.y = TFM(v.y); v.z = TFM(v.z); v.w = TFM(v.w);
      nrm[k] += v.x*v.x + v.y*v.y + v.z*v.z + v.w*v.w;
      *(float4*)(bp + sof[k]) = v;
    }
  }
  __syncthreads();

  // ---- main loop: mma(chunk c) then stage(chunk c+1) ----------------------
#pragma unroll 1
  for (int c = 0; c < NCHK; c++) {
    const uint32_t* A = (const uint32_t*)(smem + (c & 1)*BUFF) + aOff;
    const uint32_t* B = (const uint32_t*)(smem + (c & 1)*BUFF) + bOff;
#pragma unroll
    for (int kt = 0; kt < 4; kt++) {
      uint32_t a0 = A[kt*8],           a1 = A[8*STR + kt*8];
      uint32_t a2 = A[kt*8 + 4],       a3 = A[8*STR + kt*8 + 4];
#pragma unroll
      for (int j = 0; j < 9; j++) {
        uint32_t b0 = B[j*8*STR + kt*8];
        uint32_t b1 = B[j*8*STR + kt*8 + 4];
        mma8(acc[j], a0, a1, a2, a3, b0, b1);
      }
    }
    if (c + 1 < NCHK) {
      float* bp = smem + ((c + 1) & 1)*BUFF;
      int co = (c + 1)*32;
#pragma unroll
      for (int k = 0; k < 12; k++) {
        if (k >= 4 && sof[k] < 0) continue;
        float4 v = (k < 4 || goff[k] >= 0)
          ? *(const float4*)(((k < 4) ? z1 : z2) + goff[k] + co)
          : make_float4(0.f, 0.f, 0.f, 0.f);
        v.x = TFM(v.x); v.y = TFM(v.y); v.z = TFM(v.z); v.w = TFM(v.w);
        nrm[k] += v.x*v.x + v.y*v.y + v.z*v.z + v.w*v.w;
        *(float4*)(bp + sof[k]) = v;
      }
    }
    __syncthreads();
  }

  // ---- norms: reduce 8 lanes per row, write S_NRM --------------------------
#pragma unroll
  for (int k = 0; k < 12; k++) {
    float r = nrm[k];
    r += __shfl_down_sync(0xffffffffu, r, 4);
    r += __shfl_down_sync(0xffffffffu, r, 2);
    r += __shfl_down_sync(0xffffffffu, r, 1);
    int row = (tid >> 3) + 32*k;
    if (lane8 == 0 && row < ROWS) smem[S_NRM + row] = r;
  }

  // ---- sims -> smem (reuse buf0 region), stride 76 -------------------------
  {
    float* sims = smem;
    int row0 = 16*w + (lane >> 2);
    int cc = 2*(lane & 3);
#pragma unroll
    for (int j = 0; j < 9; j++) {
      *(float2*)(sims + row0*SIMSTR + 8*j + cc)       = make_float2(acc[j][0], acc[j][1]);
      *(float2*)(sims + (row0+8)*SIMSTR + 8*j + cc)   = make_float2(acc[j][2], acc[j][3]);
    }
  }
  __syncthreads();

  // invert norms in place
  for (int t = tid; t < ROWS; t += 256) {
    float v = smem[S_NRM + t];
    smem[S_NRM + t] = 1.f / fmaxf(sqrtf(v), 1e-12f);
  }
  __syncthreads();

  // ---- epilogue: per-token 25-shift softmax + weighted partials ------------
  float pA1 = 0.f, pA2 = 0.f, pP = 0.f, pS1 = 0.f, pS2 = 0.f;
  if (tid < AROWS) {
    int m = tid, ty = m >> 3, tx = m & 7;
    int mw = m >> 4;                 // warp that computed this row
    int tprime = (m >> 3) & 1;       // row parity within warp's pair
    const float inv1 = smem[S_NRM + m];
    const float* srow = smem + m*SIMSTR;
    const float* invB = smem + S_NRM + AROWS + 24*mw;
    float sn[25], mx = -1e30f;
#pragma unroll
    for (int dy = 0; dy < 5; dy++)
#pragma unroll
      for (int dx = 0; dx < 5; dx++) {
        int nl = (tprime + dy)*12 + tx + dx;
        float v = srow[nl] * inv1 * invB[nl];
        sn[dy*5 + dx] = v; mx = fmaxf(mx, v);
      }
    float se = 0.f, sv = 0.f;
    const float invT = 1.f / 0.07f;
#pragma unroll
    for (int s = 0; s < 25; s++) {
      float e = __expf((sn[s] - mx) * invT);
      se += e; sv += e * sn[s];
    }
    float sb = sv / se;
    int tok = (th0 + ty)*WW + tw0 + tx;
    float wv1 = w1[b*NN + tok], wv2 = w2[b*NN + tok];
    pA1 = (1.f - sb)*wv1; pA2 = (1.f - sb)*wv2; pP = sb; pS1 = wv1; pS2 = wv2;
  }
#pragma unroll
  for (int o = 16; o > 0; o >>= 1) {
    pA1 += __shfl_down_sync(0xffffffffu, pA1, o);
    pA2 += __shfl_down_sync(0xffffffffu, pA2, o);
    pP  += __shfl_down_sync(0xffffffffu, pP,  o);
    pS1 += __shfl_down_sync(0xffffffffu, pS1, o);
    pS2 += __shfl_down_sync(0xffffffffu, pS2, o);
  }
  float* red = smem + S_RED;
  if (lane == 0) {
    red[w] = pA1; red[8+w] = pA2; red[16+w] = pP; red[24+w] = pS1; red[32+w] = pS2;
  }
  __syncthreads();
  if (tid == 0) {
    float a1=0,a2=0,p=0,s1=0,s2=0;
#pragma unroll
    for (int i = 0; i < 8; i++) {
      a1+=red[i]; a2+=red[8+i]; p+=red[16+i]; s1+=red[24+i]; s2+=red[32+i];
    }
    int bid = blockIdx.x + 12*blockIdx.y + 72*blockIdx.z;
    g_part[0][bid]=a1; g_part[1][bid]=a2; g_part[2][bid]=p;
    g_part[3][bid]=s1; g_part[4][bid]=s2;
  }
}

__global__ void finalize_kernel(float* __restrict__ out) {
  int tid = threadIdx.x, w = tid >> 5, lane = tid & 31;
  __shared__ float sh[16];
  float a1=0,a2=0,p=0,s1=0,s2=0;
  if (w < BB) {
    for (int i = lane; i < 72; i += 32) {
      int bid = w*72 + i;
      a1 += g_part[0][bid]; a2 += g_part[1][bid]; p += g_part[2][bid];
      s1 += g_part[3][bid]; s2 += g_part[4][bid];
    }
  }
#pragma unroll
  for (int o = 16; o > 0; o >>= 1) {
    a1 += __shfl_down_sync(0xffffffffu, a1, o);
    a2 += __shfl_down_sync(0xffffffffu, a2, o);
    p  += __shfl_down_sync(0xffffffffu, p,  o);
    s1 += __shfl_down_sync(0xffffffffu, s1, o);
    s2 += __shfl_down_sync(0xffffffffu, s2, o);
  }
  if (lane == 0 && w < BB) {
    sh[w] = 0.5f*(a1/(s1 + 1e-10f) + a2/(s2 + 1e-10f));
    sh[8+w] = p;
  }
  __syncthreads();
  if (tid == 0) {
    float ta=0, tp=0;
#pragma unroll
    for (int i = 0; i < BB; i++) { ta += sh[i]; tp += sh[8+i]; }
    out[0] = ta / (float)BB;
    out[1] = tp / (float)(BB*NN);
  }
}

extern "C" void kernel_launch(void* const* d_in, const int* in_sizes, int n_in,
                              void* d_out, int out_size) {
  const float* z1 = (const float*)d_in[0];
  const float* z2 = (const float*)d_in[1];
  const float* w1 = (const float*)d_in[2];
  const float* w2 = (const float*)d_in[3];
  float* out = (float*)d_out;

  static int once = 0;
  if (!once) {
    cudaFuncSetAttribute(align_kernel,
        cudaFuncAttributeMaxDynamicSharedMemorySize, SMEMF*4);
    once = 1;
  }
  dim3 grid(12, 6, BB);   // 576 blocks; tile = 16x8 tokens
  align_kernel<<<grid, 256, SMEMF*4>>>(z1, z2, w1, w2);
  finalize_kernel<<<1, 256>>>(out);
}

// round 10
// speedup vs baseline: 1.5448x; 1.0998x over previous
#include <cuda_runtime.h>
#include <cstdint>
#include <math.h>

#define BB 8
#define HH 96
#define WW 96
#define DD 768
#define NN (HH*WW)
#define STR 36             // smem row stride (floats), ==4 mod 32 -> conflict-free frags
#define AROWS 128
#define ROWS 368           // 128 A rows + 240 B halo rows (20x12)
#define BUFF (ROWS*STR)    // 13248 floats per buffer
#define NCHK 24            // K chunks of 32 floats
#define S_NRM (2*BUFF)
#define S_RED (S_NRM+ROWS)
#define SMEMF (S_RED+48)   // 26912 floats = 107648 B
#define SIMSTR 76
#define NBLK 576
#define TFM(x) __uint_as_float(__float_as_uint(x) & 0xFFFFE000u)

__device__ float g_part[5][NBLK];
extern __shared__ float smem[];

__device__ __forceinline__ void mma8(float* d, uint32_t a0, uint32_t a1,
                                     uint32_t a2, uint32_t a3,
                                     uint32_t b0, uint32_t b1) {
  asm volatile(
    "mma.sync.aligned.m16n8k8.row.col.f32.tf32.tf32.f32 "
    "{%0,%1,%2,%3}, {%4,%5,%6,%7}, {%8,%9}, {%0,%1,%2,%3};"
    : "+f"(d[0]), "+f"(d[1]), "+f"(d[2]), "+f"(d[3])
    : "r"(a0), "r"(a1), "r"(a2), "r"(a3), "r"(b0), "r"(b1));
}

__global__ void __launch_bounds__(256, 2)
align_kernel(const float* __restrict__ z1, const float* __restrict__ z2,
             const float* __restrict__ w1, const float* __restrict__ w2)
{
  const int tid = threadIdx.x, w = tid >> 5, lane = tid & 31, lane8 = tid & 7;
  const int b = blockIdx.z, th0 = blockIdx.y * 16, tw0 = blockIdx.x * 8;

  // ---- A staging: affine in slot k (rows arow+32k, k=0..3) -----------------
  const int arow = tid >> 3;                 // 0..31
  const int aty  = tid >> 6;                 // 0..3
  const int atx  = (tid >> 3) & 7;
  const int agBase  = (b*NN + (th0+aty)*WW + tw0+atx)*DD + lane8*4;
  const int agStep  = 4*WW*DD;               // +4 token rows per slot
  const int sofBase = arow*STR + lane8*4;
  const int sofStep = 32*STR;

  // ---- B staging: slot k=0..7 -> halo row n = arow + 32k -------------------
  int bg[8];
#pragma unroll
  for (int k = 0; k < 8; k++) {
    int n = arow + 32*k;
    if (n < 240) {
      int r = n/12, cl = n - 12*r;
      int gh = th0 + r - 2, gw = tw0 + cl - 2;
      bool inb = ((unsigned)gh < HH) && ((unsigned)gw < WW);
      bg[k] = inb ? (b*NN + gh*WW + gw)*DD + lane8*4 : -1;  // -1: OOB (zero)
    } else bg[k] = -2;                                       // idle slot
  }
  float nrmA[4] = {0,0,0,0};
  float nrmB[8] = {0,0,0,0,0,0,0,0};
  float acc[9][4];
#pragma unroll
  for (int j = 0; j < 9; j++)
#pragma unroll
    for (int i = 0; i < 4; i++) acc[j][i] = 0.f;

  const int aOff = (16*w + (lane >> 2))*STR + (lane & 3);
  const int bOff = (AROWS + 24*w + (lane >> 2))*STR + (lane & 3);

  // ---- prologue: zero OOB halo rows in BOTH buffers (stores only once) -----
#pragma unroll
  for (int k = 0; k < 8; k++)
    if (bg[k] == -1) {
      int sof = sofBase + (4+k)*sofStep;
      *(float4*)(smem + sof)        = make_float4(0.f,0.f,0.f,0.f);
      *(float4*)(smem + BUFF + sof) = make_float4(0.f,0.f,0.f,0.f);
    }
  // stage chunk 0 into buf0
#pragma unroll
  for (int k = 0; k < 4; k++) {
    float4 v = *(const float4*)(z1 + agBase + k*agStep);
    v.x=TFM(v.x); v.y=TFM(v.y); v.z=TFM(v.z); v.w=TFM(v.w);
    nrmA[k] += v.x*v.x + v.y*v.y + v.z*v.z + v.w*v.w;
    *(float4*)(smem + sofBase + k*sofStep) = v;
  }
#pragma unroll
  for (int k = 0; k < 8; k++)
    if (bg[k] >= 0) {
      float4 v = *(const float4*)(z2 + bg[k]);
      v.x=TFM(v.x); v.y=TFM(v.y); v.z=TFM(v.z); v.w=TFM(v.w);
      nrmB[k] += v.x*v.x + v.y*v.y + v.z*v.z + v.w*v.w;
      *(float4*)(smem + sofBase + (4+k)*sofStep) = v;
    }
  __syncthreads();

  // ---- main loop: 2-phase register prefetch interleaved with MMA halves ----
#pragma unroll 1
  for (int c = 0; c < NCHK; c++) {
    const uint32_t* A = (const uint32_t*)(smem + (c & 1)*BUFF) + aOff;
    const uint32_t* B = (const uint32_t*)(smem + (c & 1)*BUFF) + bOff;
    float* nb = smem + ((c + 1) & 1)*BUFF;
    const bool more = (c + 1 < NCHK);
    const int co = (c + 1)*32;
    float4 zb[6];

    // phase-A prefetch: A slots 0..3 + B slots 0..1
    if (more) {
#pragma unroll
      for (int k = 0; k < 4; k++)
        zb[k] = *(const float4*)(z1 + agBase + k*agStep + co);
#pragma unroll
      for (int k = 0; k < 2; k++)
        if (bg[k] >= 0) zb[4+k] = *(const float4*)(z2 + bg[k] + co);
    }
    // MMA kt = 0,1
#pragma unroll
    for (int kt = 0; kt < 2; kt++) {
      uint32_t a0 = A[kt*8],     a1 = A[8*STR + kt*8];
      uint32_t a2 = A[kt*8 + 4], a3 = A[8*STR + kt*8 + 4];
#pragma unroll
      for (int j = 0; j < 9; j++)
        mma8(acc[j], a0, a1, a2, a3, B[j*8*STR + kt*8], B[j*8*STR + kt*8 + 4]);
    }
    // STS phase-A + prefetch phase-B (B slots 2..7)
    if (more) {
#pragma unroll
      for (int k = 0; k < 4; k++) {
        float4 v = zb[k];
        v.x=TFM(v.x); v.y=TFM(v.y); v.z=TFM(v.z); v.w=TFM(v.w);
        nrmA[k] += v.x*v.x + v.y*v.y + v.z*v.z + v.w*v.w;
        *(float4*)(nb + sofBase + k*sofStep) = v;
      }
#pragma unroll
      for (int k = 0; k < 2; k++)
        if (bg[k] >= 0) {
          float4 v = zb[4+k];
          v.x=TFM(v.x); v.y=TFM(v.y); v.z=TFM(v.z); v.w=TFM(v.w);
          nrmB[k] += v.x*v.x + v.y*v.y + v.z*v.z + v.w*v.w;
          *(float4*)(nb + sofBase + (4+k)*sofStep) = v;
        }
#pragma unroll
      for (int k = 2; k < 8; k++)
        if (bg[k] >= 0) zb[k-2] = *(const float4*)(z2 + bg[k] + co);
    }
    // MMA kt = 2,3
#pragma unroll
    for (int kt = 2; kt < 4; kt++) {
      uint32_t a0 = A[kt*8],     a1 = A[8*STR + kt*8];
      uint32_t a2 = A[kt*8 + 4], a3 = A[8*STR + kt*8 + 4];
#pragma unroll
      for (int j = 0; j < 9; j++)
        mma8(acc[j], a0, a1, a2, a3, B[j*8*STR + kt*8], B[j*8*STR + kt*8 + 4]);
    }
    // STS phase-B
    if (more) {
#pragma unroll
      for (int k = 2; k < 8; k++)
        if (bg[k] >= 0) {
          float4 v = zb[k-2];
          v.x=TFM(v.x); v.y=TFM(v.y); v.z=TFM(v.z); v.w=TFM(v.w);
          nrmB[k] += v.x*v.x + v.y*v.y + v.z*v.z + v.w*v.w;
          *(float4*)(nb + sofBase + (4+k)*sofStep) = v;
        }
    }
    __syncthreads();
  }

  // ---- norms: reduce 8 lanes per row -> S_NRM ------------------------------
#pragma unroll
  for (int k = 0; k < 4; k++) {
    float r = nrmA[k];
    r += __shfl_down_sync(0xffffffffu, r, 4);
    r += __shfl_down_sync(0xffffffffu, r, 2);
    r += __shfl_down_sync(0xffffffffu, r, 1);
    if (lane8 == 0) smem[S_NRM + arow + 32*k] = r;
  }
#pragma unroll
  for (int k = 0; k < 8; k++) {
    float r = nrmB[k];
    r += __shfl_down_sync(0xffffffffu, r, 4);
    r += __shfl_down_sync(0xffffffffu, r, 2);
    r += __shfl_down_sync(0xffffffffu, r, 1);
    int row = AROWS + arow + 32*k;
    if (lane8 == 0 && row < ROWS) smem[S_NRM + row] = r;
  }

  // ---- sims -> smem (reuse buf0 region), stride 76 -------------------------
  {
    float* sims = smem;
    int row0 = 16*w + (lane >> 2);
    int cc = 2*(lane & 3);
#pragma unroll
    for (int j = 0; j < 9; j++) {
      *(float2*)(sims + row0*SIMSTR + 8*j + cc)     = make_float2(acc[j][0], acc[j][1]);
      *(float2*)(sims + (row0+8)*SIMSTR + 8*j + cc) = make_float2(acc[j][2], acc[j][3]);
    }
  }
  __syncthreads();

  for (int t = tid; t < ROWS; t += 256) {
    float v = smem[S_NRM + t];
    smem[S_NRM + t] = 1.f / fmaxf(sqrtf(v), 1e-12f);
  }
  __syncthreads();

  // ---- epilogue: per-token 25-shift softmax + weighted partials ------------
  float pA1 = 0.f, pA2 = 0.f, pP = 0.f, pS1 = 0.f, pS2 = 0.f;
  if (tid < AROWS) {
    int m = tid, ty = m >> 3, tx = m & 7;
    int mw = m >> 4;
    int tprime = (m >> 3) & 1;
    const float inv1 = smem[S_NRM + m];
    const float* srow = smem + m*SIMSTR;
    const float* invB = smem + S_NRM + AROWS + 24*mw;
    float sn[25], mx = -1e30f;
#pragma unroll
    for (int dy = 0; dy < 5; dy++)
#pragma unroll
      for (int dx = 0; dx < 5; dx++) {
        int nl = (tprime + dy)*12 + tx + dx;
        float v = srow[nl] * inv1 * invB[nl];
        sn[dy*5 + dx] = v; mx = fmaxf(mx, v);
      }
    float se = 0.f, sv = 0.f;
    const float invT = 1.f / 0.07f;
#pragma unroll
    for (int s = 0; s < 25; s++) {
      float e = __expf((sn[s] - mx) * invT);
      se += e; sv += e * sn[s];
    }
    float sb = sv / se;
    int tok = (th0 + ty)*WW + tw0 + tx;
    float wv1 = w1[b*NN + tok], wv2 = w2[b*NN + tok];
    pA1 = (1.f - sb)*wv1; pA2 = (1.f - sb)*wv2; pP = sb; pS1 = wv1; pS2 = wv2;
  }
#pragma unroll
  for (int o = 16; o > 0; o >>= 1) {
    pA1 += __shfl_down_sync(0xffffffffu, pA1, o);
    pA2 += __shfl_down_sync(0xffffffffu, pA2, o);
    pP  += __shfl_down_sync(0xffffffffu, pP,  o);
    pS1 += __shfl_down_sync(0xffffffffu, pS1, o);
    pS2 += __shfl_down_sync(0xffffffffu, pS2, o);
  }
  float* red = smem + S_RED;
  if (lane == 0) {
    red[w] = pA1; red[8+w] = pA2; red[16+w] = pP; red[24+w] = pS1; red[32+w] = pS2;
  }
  __syncthreads();
  if (tid == 0) {
    float a1=0,a2=0,p=0,s1=0,s2=0;
#pragma unroll
    for (int i = 0; i < 8; i++) {
      a1+=red[i]; a2+=red[8+i]; p+=red[16+i]; s1+=red[24+i]; s2+=red[32+i];
    }
    int bid = blockIdx.x + 12*blockIdx.y + 72*blockIdx.z;
    g_part[0][bid]=a1; g_part[1][bid]=a2; g_part[2][bid]=p;
    g_part[3][bid]=s1; g_part[4][bid]=s2;
  }
}

__global__ void finalize_kernel(float* __restrict__ out) {
  int tid = threadIdx.x, w = tid >> 5, lane = tid & 31;
  __shared__ float sh[16];
  float a1=0,a2=0,p=0,s1=0,s2=0;
  if (w < BB) {
    for (int i = lane; i < 72; i += 32) {
      int bid = w*72 + i;
      a1 += g_part[0][bid]; a2 += g_part[1][bid]; p += g_part[2][bid];
      s1 += g_part[3][bid]; s2 += g_part[4][bid];
    }
  }
#pragma unroll
  for (int o = 16; o > 0; o >>= 1) {
    a1 += __shfl_down_sync(0xffffffffu, a1, o);
    a2 += __shfl_down_sync(0xffffffffu, a2, o);
    p  += __shfl_down_sync(0xffffffffu, p,  o);
    s1 += __shfl_down_sync(0xffffffffu, s1, o);
    s2 += __shfl_down_sync(0xffffffffu, s2, o);
  }
  if (lane == 0 && w < BB) {
    sh[w] = 0.5f*(a1/(s1 + 1e-10f) + a2/(s2 + 1e-10f));
    sh[8+w] = p;
  }
  __syncthreads();
  if (tid == 0) {
    float ta=0, tp=0;
#pragma unroll
    for (int i = 0; i < BB; i++) { ta += sh[i]; tp += sh[8+i]; }
    out[0] = ta / (float)BB;
    out[1] = tp / (float)(BB*NN);
  }
}

extern "C" void kernel_launch(void* const* d_in, const int* in_sizes, int n_in,
                              void* d_out, int out_size) {
  const float* z1 = (const float*)d_in[0];
  const float* z2 = (const float*)d_in[1];
  const float* w1 = (const float*)d_in[2];
  const float* w2 = (const float*)d_in[3];
  float* out = (float*)d_out;

  static int once = 0;
  if (!once) {
    cudaFuncSetAttribute(align_kernel,
        cudaFuncAttributeMaxDynamicSharedMemorySize, SMEMF*4);
    once = 1;
  }
  dim3 grid(12, 6, BB);   // 576 blocks; tile = 16x8 tokens
  align_kernel<<<grid, 256, SMEMF*4>>>(z1, z2, w1, w2);
  finalize_kernel<<<1, 256>>>(out);
}